// round 9
// baseline (speedup 1.0000x reference)
#include <cuda_runtime.h>
#include <math.h>
#include <stdint.h>

#define BSZ 64
#define NSEQ 196
#define CC 768
#define C3 2304
#define MROWS 12544

#define SCAN_BLOCKS 128
#define SCAN_THREADS 384
#define WH_FLOATS (18 * 768)
#define HSB (64 * 132)                 /* one h buffer (padded) */
#define HS_FLOATS (2 * HSB)            /* double-buffered */
#define PART_FLOATS (18 * 64 * 8)
#define SCAN_SMEM_BYTES ((WH_FLOATS + HS_FLOATS + PART_FLOATS) * 4)

// -------- persistent scratch (module globals; no runtime allocation) --------
// __device__ globals are zero-initialized at module load; reset_kernel
// re-zeroes the mutable state after every scan so graph replays are identical.
__device__ float g_xzrn[(size_t)MROWS * C3];   // [t][b][3C]  time-major
__device__ float g_hs[(size_t)MROWS * CC];     // [t][b][C]   time-major
__device__ float g_h[2][BSZ * CC];             // ping-pong hidden state
__device__ unsigned int g_flag[SCAN_BLOCKS];   // per-CTA arrival flags

__device__ __forceinline__ unsigned ldcg_u32(const unsigned* p) {
  unsigned v; asm volatile("ld.global.cg.u32 %0, [%1];" : "=r"(v) : "l"(p)); return v;
}
__device__ __forceinline__ void stcg_u32(unsigned* p, unsigned v) {
  asm volatile("st.global.cg.u32 [%0], %1;" :: "l"(p), "r"(v));
}

// ---------------------------------------------------------------------------
// reset: runs AFTER the scan. Re-zeroes h0 and the flags for the next replay.
// ---------------------------------------------------------------------------
__global__ void reset_kernel() {
  int i = blockIdx.x * blockDim.x + threadIdx.x;
  if (i < BSZ * CC) g_h[0][i] = 0.f;
  if (i < SCAN_BLOCKS) g_flag[i] = 0u;
}

// ---------------------------------------------------------------------------
// SGEMM (R8-proven): Co[remap(m)][d] = sum_k A[m][k]*Bw[d][k] (+ bias[d])
// remap(m) = (m % P) * Q + m / P.  128x128 tile, BK=8, 256 thr, 8x8 microtile,
// double-buffered smem (one sync per k-chunk), 2 CTAs/SM.
// ---------------------------------------------------------------------------
__global__ __launch_bounds__(256, 2) void sgemm_kernel(
    const float* __restrict__ A, const float* __restrict__ Bw,
    const float* __restrict__ bias, float* __restrict__ Co,
    int K, int D, int P, int Q)
{
  __shared__ float As[2][8][128];
  __shared__ float Bs[2][8][128];
  const int t  = threadIdx.x;
  const int m0 = blockIdx.y * 128;
  const int d0 = blockIdx.x * 128;
  const int lr = t >> 1;
  const int lk = (t & 1) * 4;
  const float* ap = A  + (size_t)(m0 + lr) * K + lk;
  const float* bp = Bw + (size_t)(d0 + lr) * K + lk;
  const int tx = t & 15, ty = t >> 4;

  float acc[8][8];
#pragma unroll
  for (int i = 0; i < 8; ++i)
#pragma unroll
    for (int j = 0; j < 8; ++j) acc[i][j] = 0.f;

  {
    float4 av = *(const float4*)ap;
    float4 bv = *(const float4*)bp;
    As[0][lk + 0][lr] = av.x; As[0][lk + 1][lr] = av.y;
    As[0][lk + 2][lr] = av.z; As[0][lk + 3][lr] = av.w;
    Bs[0][lk + 0][lr] = bv.x; Bs[0][lk + 1][lr] = bv.y;
    Bs[0][lk + 2][lr] = bv.z; Bs[0][lk + 3][lr] = bv.w;
  }
  __syncthreads();

  int buf = 0;
  for (int k0 = 0; k0 < K; k0 += 8) {
    const bool more = (k0 + 8 < K);
    float4 av, bv;
    if (more) {
      av = *(const float4*)(ap + k0 + 8);
      bv = *(const float4*)(bp + k0 + 8);
    }
#pragma unroll
    for (int kk = 0; kk < 8; ++kk) {
      float a[8], b[8];
      *(float4*)(a)     = *(const float4*)&As[buf][kk][ty * 4];
      *(float4*)(a + 4) = *(const float4*)&As[buf][kk][64 + ty * 4];
      *(float4*)(b)     = *(const float4*)&Bs[buf][kk][tx * 4];
      *(float4*)(b + 4) = *(const float4*)&Bs[buf][kk][64 + tx * 4];
#pragma unroll
      for (int i = 0; i < 8; ++i)
#pragma unroll
        for (int j = 0; j < 8; ++j)
          acc[i][j] += a[i] * b[j];
    }
    if (more) {
      const int nb = buf ^ 1;
      As[nb][lk + 0][lr] = av.x; As[nb][lk + 1][lr] = av.y;
      As[nb][lk + 2][lr] = av.z; As[nb][lk + 3][lr] = av.w;
      Bs[nb][lk + 0][lr] = bv.x; Bs[nb][lk + 1][lr] = bv.y;
      Bs[nb][lk + 2][lr] = bv.z; Bs[nb][lk + 3][lr] = bv.w;
      __syncthreads();
      buf = nb;
    }
  }

  float bvs[8];
#pragma unroll
  for (int j = 0; j < 8; ++j) {
    int col = (j < 4) ? (tx * 4 + j) : (64 + tx * 4 + (j - 4));
    bvs[j] = bias ? bias[d0 + col] : 0.f;
  }
#pragma unroll
  for (int i = 0; i < 8; ++i) {
    int row = (i < 4) ? (ty * 4 + i) : (64 + ty * 4 + (i - 4));
    int m = m0 + row;
    int rm = (m % P) * Q + m / P;
    float* orow = Co + (size_t)rm * D + d0;
    float4 v0 = make_float4(acc[i][0] + bvs[0], acc[i][1] + bvs[1],
                            acc[i][2] + bvs[2], acc[i][3] + bvs[3]);
    float4 v1 = make_float4(acc[i][4] + bvs[4], acc[i][5] + bvs[5],
                            acc[i][6] + bvs[6], acc[i][7] + bvs[7]);
    *(float4*)(orow + tx * 4)      = v0;
    *(float4*)(orow + 64 + tx * 4) = v1;
  }
}

// ---------------------------------------------------------------------------
// Persistent GRU scan — structure identical to R7/R8 except the grid barrier:
// R9 delta ONLY: distributed flag barrier (parallel st.cg arrives to distinct
// addresses; every CTA polls all 128 flags with 128 threads, ld.cg, no RMW).
// ---------------------------------------------------------------------------
__global__ __launch_bounds__(SCAN_THREADS, 1) void scan_kernel(
    const float* __restrict__ Wh, const float* __restrict__ bh)
{
  extern __shared__ float smem[];
  float* Wh_s = smem;                         // [18][768]
  float* h_s  = smem + WH_FLOATS;             // [2][64][132] padded
  float* p_s  = smem + WH_FLOATS + HS_FLOATS; // [18*64][8] partials

  const int tid = threadIdx.x;
  const int c0  = blockIdx.x * 6;
  const int bg  = tid & 7;
  const int j   = (tid >> 3) % 6;
  const int ks  = tid / 48;                   // 0..7: k-slice of 16 per tile

  for (int i = tid; i < WH_FLOATS; i += SCAN_THREADS) {
    int r = i / 768, k = i - r * 768;
    int g = r / 6, jj = r - g * 6;
    Wh_s[i] = Wh[(size_t)(g * 768 + c0 + jj) * 768 + k];
  }
  const int je = tid >> 6;                    // epilogue identity 0..5
  const int be = tid & 63;
  const int ce = c0 + je;
  const float bz = bh[ce];
  const float br = bh[768 + ce];
  const float bn = bh[1536 + ce];
  __syncthreads();

  const float* wzp = Wh_s + (j)      * 768;
  const float* wrp = Wh_s + (6 + j)  * 768;
  const float* wnp = Wh_s + (12 + j) * 768;

  for (int s = 0; s < NSEQ; ++s) {
    const float* hsrc = g_h[s & 1];
    float*       hdst = g_h[(s + 1) & 1];

    // ---- stage tile 0 into buffer 0 ----
    float4 pf[6];
#pragma unroll
    for (int u = 0; u < 6; ++u) {
      int i = tid + SCAN_THREADS * u;
      if (i < 2048) {
        int bb = i >> 5, kq = i & 31;
        pf[u] = __ldcg((const float4*)(hsrc + bb * CC + kq * 4));
      }
    }
#pragma unroll
    for (int u = 0; u < 6; ++u) {
      int i = tid + SCAN_THREADS * u;
      if (i < 2048) {
        int bb = i >> 5, kq = i & 31;
        *(float4*)(h_s + bb * 132 + kq * 4) = pf[u];
      }
    }
    __syncthreads();

    float az[8], ar[8], an[8];
#pragma unroll
    for (int bb = 0; bb < 8; ++bb) { az[bb] = 0.f; ar[bb] = 0.f; an[bb] = 0.f; }

    int buf = 0;
    for (int kt = 0; kt < 6; ++kt) {
      if (kt < 5) {
#pragma unroll
        for (int u = 0; u < 6; ++u) {
          int i = tid + SCAN_THREADS * u;
          if (i < 2048) {
            int bb = i >> 5, kq = i & 31;
            pf[u] = __ldcg((const float4*)(hsrc + bb * CC + (kt + 1) * 128 + kq * 4));
          }
        }
      }

      const int kof = kt * 128 + ks * 16;
      const int hof = ks * 16;
      const float* hbuf = h_s + buf * HSB;
#pragma unroll
      for (int q = 0; q < 4; ++q) {
        float4 wz = *(const float4*)(wzp + kof + q * 4);
        float4 wr = *(const float4*)(wrp + kof + q * 4);
        float4 wn = *(const float4*)(wnp + kof + q * 4);
#pragma unroll
        for (int bb = 0; bb < 8; ++bb) {
          float4 hv = *(const float4*)(hbuf + (bg + 8 * bb) * 132 + hof + q * 4);
          az[bb] = fmaf(hv.x, wz.x, fmaf(hv.y, wz.y,
                   fmaf(hv.z, wz.z, fmaf(hv.w, wz.w, az[bb]))));
          ar[bb] = fmaf(hv.x, wr.x, fmaf(hv.y, wr.y,
                   fmaf(hv.z, wr.z, fmaf(hv.w, wr.w, ar[bb]))));
          an[bb] = fmaf(hv.x, wn.x, fmaf(hv.y, wn.y,
                   fmaf(hv.z, wn.z, fmaf(hv.w, wn.w, an[bb]))));
        }
      }

      __syncthreads();
      if (kt < 5) {
#pragma unroll
        for (int u = 0; u < 6; ++u) {
          int i = tid + SCAN_THREADS * u;
          if (i < 2048) {
            int bb = i >> 5, kq = i & 31;
            *(float4*)(h_s + (buf ^ 1) * HSB + bb * 132 + kq * 4) = pf[u];
          }
        }
      }
      __syncthreads();
      buf ^= 1;
    }

#pragma unroll
    for (int bb = 0; bb < 8; ++bb) {
      const int b = bg + 8 * bb;
      p_s[((0 * 6 + j) * 64 + b) * 8 + ks] = az[bb];
      p_s[((1 * 6 + j) * 64 + b) * 8 + ks] = ar[bb];
      p_s[((2 * 6 + j) * 64 + b) * 8 + ks] = an[bb];
    }
    __syncthreads();

    float hz, hr, hn;
    {
      const float* pz = p_s + ((0 * 6 + je) * 64 + be) * 8;
      const float* pr = p_s + ((1 * 6 + je) * 64 + be) * 8;
      const float* pn = p_s + ((2 * 6 + je) * 64 + be) * 8;
      float4 a0 = *(const float4*)(pz), a1 = *(const float4*)(pz + 4);
      float4 b0 = *(const float4*)(pr), b1 = *(const float4*)(pr + 4);
      float4 d0 = *(const float4*)(pn), d1 = *(const float4*)(pn + 4);
      hz = (a0.x + a0.y + a0.z + a0.w) + (a1.x + a1.y + a1.z + a1.w);
      hr = (b0.x + b0.y + b0.z + b0.w) + (b1.x + b1.y + b1.z + b1.w);
      hn = (d0.x + d0.y + d0.z + d0.w) + (d1.x + d1.y + d1.z + d1.w);
    }

    const size_t xrow = (size_t)(s * BSZ + be) * C3;
    float xz = g_xzrn[xrow + ce];
    float xr = g_xzrn[xrow + 768 + ce];
    float xn = g_xzrn[xrow + 1536 + ce];
    float hold = __ldcg(hsrc + be * CC + ce);

    float z  = 1.f / (1.f + expf(-(xz + hz + bz)));
    float rr = 1.f / (1.f + expf(-(xr + hr + br)));
    float nc = tanhf(xn + rr * (hn + bn));
    float hnew = (1.f - z) * nc + z * hold;

    __stcg(hdst + be * CC + ce, hnew);
    g_hs[(size_t)(s * BSZ + be) * CC + ce] = hnew;

    // ---- distributed flag barrier (R9) ----
    __threadfence();
    __syncthreads();
    if (tid == 0) stcg_u32(&g_flag[blockIdx.x], (unsigned)(s + 1));
    if (tid < SCAN_BLOCKS) {
      const unsigned tgt = (unsigned)(s + 1);
      while (ldcg_u32(&g_flag[tid]) < tgt) { __nanosleep(32); }
    }
    __syncthreads();
  }
}

// ---------------------------------------------------------------------------
extern "C" void kernel_launch(void* const* d_in, const int* in_sizes, int n_in,
                              void* d_out, int out_size) {
  const float* x  = (const float*)d_in[0];
  const float* Wx = (const float*)d_in[1];
  const float* bx = (const float*)d_in[2];
  const float* Wh = (const float*)d_in[3];
  const float* bh = (const float*)d_in[4];
  const float* Wp = (const float*)d_in[5];
  float* out = (float*)d_out;

  void *p_xzrn = nullptr, *p_hs = nullptr;
  cudaGetSymbolAddress(&p_xzrn, g_xzrn);
  cudaGetSymbolAddress(&p_hs, g_hs);

  cudaFuncSetAttribute(scan_kernel,
                       cudaFuncAttributeMaxDynamicSharedMemorySize,
                       SCAN_SMEM_BYTES);

  // GEMM1: x_zrn[(n*64+b)][3C] = seq @ Wx^T + bx   (P=196, Q=64 remap)
  sgemm_kernel<<<dim3(C3 / 128, MROWS / 128), 256>>>(
      x, Wx, bx, (float*)p_xzrn, CC, C3, NSEQ, BSZ);

  // recurrence
  scan_kernel<<<SCAN_BLOCKS, SCAN_THREADS, SCAN_SMEM_BYTES>>>(Wh, bh);

  // GEMM3: out[b*196+n][C] = hs @ Wp^T              (P=64, Q=196 remap)
  sgemm_kernel<<<dim3(CC / 128, MROWS / 128), 256>>>(
      (const float*)p_hs, Wp, nullptr, out, CC, CC, BSZ, NSEQ);

  // reset scan state for the next replay
  reset_kernel<<<(BSZ * CC + 255) / 256, 256>>>();
}

// round 11
// speedup vs baseline: 1.5304x; 1.5304x over previous
#include <cuda_runtime.h>
#include <math.h>
#include <stdint.h>

#define BSZ 64
#define NSEQ 196
#define CC 768
#define C3 2304
#define MROWS 12544

#define SCAN_BLOCKS 128
#define SCAN_THREADS 384
#define WH_FLOATS (18 * 768)
#define HSB (64 * 132)                 /* one h buffer (padded) */
#define HS_FLOATS (2 * HSB)            /* double-buffered */
#define PART_FLOATS (18 * 64 * 8)
#define SCAN_SMEM_BYTES ((WH_FLOATS + HS_FLOATS + PART_FLOATS) * 4)

// -------- persistent scratch (module globals; no runtime allocation) --------
// __device__ globals are zero-initialized at module load; reset_kernel
// re-zeroes the mutable state after every scan so graph replays are identical.
__device__ float g_xzrn[(size_t)MROWS * C3];   // [t][b][3C]  time-major
__device__ float g_hs[(size_t)MROWS * CC];     // [t][b][C]   time-major
__device__ float g_h[2][BSZ * CC];             // ping-pong hidden state
__device__ unsigned int g_bar;

__device__ __forceinline__ unsigned ldcg_u32(const unsigned* p) {
  unsigned v; asm volatile("ld.global.cg.u32 %0, [%1];" : "=r"(v) : "l"(p)); return v;
}

// ---------------------------------------------------------------------------
// reset: runs AFTER the scan. Re-zeroes h0 and the barrier for the next replay.
// ---------------------------------------------------------------------------
__global__ void reset_kernel() {
  int i = blockIdx.x * blockDim.x + threadIdx.x;
  if (i < BSZ * CC) g_h[0][i] = 0.f;
  if (i == 0) g_bar = 0u;
}

// ---------------------------------------------------------------------------
// SGEMM (R8-proven): Co[remap(m)][d] = sum_k A[m][k]*Bw[d][k] (+ bias[d])
// remap(m) = (m % P) * Q + m / P.  128x128 tile, BK=8, 256 thr, 8x8 microtile,
// double-buffered smem (one sync per k-chunk), 2 CTAs/SM.
// ---------------------------------------------------------------------------
__global__ __launch_bounds__(256, 2) void sgemm_kernel(
    const float* __restrict__ A, const float* __restrict__ Bw,
    const float* __restrict__ bias, float* __restrict__ Co,
    int K, int D, int P, int Q)
{
  __shared__ float As[2][8][128];
  __shared__ float Bs[2][8][128];
  const int t  = threadIdx.x;
  const int m0 = blockIdx.y * 128;
  const int d0 = blockIdx.x * 128;
  const int lr = t >> 1;
  const int lk = (t & 1) * 4;
  const float* ap = A  + (size_t)(m0 + lr) * K + lk;
  const float* bp = Bw + (size_t)(d0 + lr) * K + lk;
  const int tx = t & 15, ty = t >> 4;

  float acc[8][8];
#pragma unroll
  for (int i = 0; i < 8; ++i)
#pragma unroll
    for (int j = 0; j < 8; ++j) acc[i][j] = 0.f;

  {
    float4 av = *(const float4*)ap;
    float4 bv = *(const float4*)bp;
    As[0][lk + 0][lr] = av.x; As[0][lk + 1][lr] = av.y;
    As[0][lk + 2][lr] = av.z; As[0][lk + 3][lr] = av.w;
    Bs[0][lk + 0][lr] = bv.x; Bs[0][lk + 1][lr] = bv.y;
    Bs[0][lk + 2][lr] = bv.z; Bs[0][lk + 3][lr] = bv.w;
  }
  __syncthreads();

  int buf = 0;
  for (int k0 = 0; k0 < K; k0 += 8) {
    const bool more = (k0 + 8 < K);
    float4 av, bv;
    if (more) {
      av = *(const float4*)(ap + k0 + 8);
      bv = *(const float4*)(bp + k0 + 8);
    }
#pragma unroll
    for (int kk = 0; kk < 8; ++kk) {
      float a[8], b[8];
      *(float4*)(a)     = *(const float4*)&As[buf][kk][ty * 4];
      *(float4*)(a + 4) = *(const float4*)&As[buf][kk][64 + ty * 4];
      *(float4*)(b)     = *(const float4*)&Bs[buf][kk][tx * 4];
      *(float4*)(b + 4) = *(const float4*)&Bs[buf][kk][64 + tx * 4];
#pragma unroll
      for (int i = 0; i < 8; ++i)
#pragma unroll
        for (int j = 0; j < 8; ++j)
          acc[i][j] += a[i] * b[j];
    }
    if (more) {
      const int nb = buf ^ 1;
      As[nb][lk + 0][lr] = av.x; As[nb][lk + 1][lr] = av.y;
      As[nb][lk + 2][lr] = av.z; As[nb][lk + 3][lr] = av.w;
      Bs[nb][lk + 0][lr] = bv.x; Bs[nb][lk + 1][lr] = bv.y;
      Bs[nb][lk + 2][lr] = bv.z; Bs[nb][lk + 3][lr] = bv.w;
      __syncthreads();
      buf = nb;
    }
  }

  float bvs[8];
#pragma unroll
  for (int j = 0; j < 8; ++j) {
    int col = (j < 4) ? (tx * 4 + j) : (64 + tx * 4 + (j - 4));
    bvs[j] = bias ? bias[d0 + col] : 0.f;
  }
#pragma unroll
  for (int i = 0; i < 8; ++i) {
    int row = (i < 4) ? (ty * 4 + i) : (64 + ty * 4 + (i - 4));
    int m = m0 + row;
    int rm = (m % P) * Q + m / P;
    float* orow = Co + (size_t)rm * D + d0;
    float4 v0 = make_float4(acc[i][0] + bvs[0], acc[i][1] + bvs[1],
                            acc[i][2] + bvs[2], acc[i][3] + bvs[3]);
    float4 v1 = make_float4(acc[i][4] + bvs[4], acc[i][5] + bvs[5],
                            acc[i][6] + bvs[6], acc[i][7] + bvs[7]);
    *(float4*)(orow + tx * 4)      = v0;
    *(float4*)(orow + 64 + tx * 4) = v1;
  }
}

// ---------------------------------------------------------------------------
// Persistent GRU scan — R8 structure verbatim (two syncs per kt tile,
// __threadfence release). R11 deltas ONLY:
//   (a) x/h_old prefetched at step top (hidden under tile-0 staging),
//   (b) uncoalesced g_hs store moved after the arrive (overlaps poll),
//   (c) poll is a pure ld.cg spin (no __nanosleep quantization).
// ---------------------------------------------------------------------------
__global__ __launch_bounds__(SCAN_THREADS, 1) void scan_kernel(
    const float* __restrict__ Wh, const float* __restrict__ bh)
{
  extern __shared__ float smem[];
  float* Wh_s = smem;                         // [18][768]
  float* h_s  = smem + WH_FLOATS;             // [2][64][132] padded
  float* p_s  = smem + WH_FLOATS + HS_FLOATS; // [18*64][8] partials

  const int tid = threadIdx.x;
  const int c0  = blockIdx.x * 6;
  const int bg  = tid & 7;
  const int j   = (tid >> 3) % 6;
  const int ks  = tid / 48;                   // 0..7: k-slice of 16 per tile

  for (int i = tid; i < WH_FLOATS; i += SCAN_THREADS) {
    int r = i / 768, k = i - r * 768;
    int g = r / 6, jj = r - g * 6;
    Wh_s[i] = Wh[(size_t)(g * 768 + c0 + jj) * 768 + k];
  }
  const int je = tid >> 6;                    // epilogue identity 0..5
  const int be = tid & 63;
  const int ce = c0 + je;
  const float bz = bh[ce];
  const float br = bh[768 + ce];
  const float bn = bh[1536 + ce];
  __syncthreads();

  const float* wzp = Wh_s + (j)      * 768;
  const float* wrp = Wh_s + (6 + j)  * 768;
  const float* wnp = Wh_s + (12 + j) * 768;

  for (int s = 0; s < NSEQ; ++s) {
    const float* hsrc = g_h[s & 1];
    float*       hdst = g_h[(s + 1) & 1];

    // (a) prefetch epilogue operands at step top
    const size_t xrow = (size_t)(s * BSZ + be) * C3;
    float xz   = __ldcg(g_xzrn + xrow + ce);
    float xr   = __ldcg(g_xzrn + xrow + 768 + ce);
    float xn   = __ldcg(g_xzrn + xrow + 1536 + ce);
    float hold = __ldcg(hsrc + be * CC + ce);

    // ---- stage tile 0 into buffer 0 ----
    float4 pf[6];
#pragma unroll
    for (int u = 0; u < 6; ++u) {
      int i = tid + SCAN_THREADS * u;
      if (i < 2048) {
        int bb = i >> 5, kq = i & 31;
        pf[u] = __ldcg((const float4*)(hsrc + bb * CC + kq * 4));
      }
    }
#pragma unroll
    for (int u = 0; u < 6; ++u) {
      int i = tid + SCAN_THREADS * u;
      if (i < 2048) {
        int bb = i >> 5, kq = i & 31;
        *(float4*)(h_s + bb * 132 + kq * 4) = pf[u];
      }
    }
    __syncthreads();

    float az[8], ar[8], an[8];
#pragma unroll
    for (int bb = 0; bb < 8; ++bb) { az[bb] = 0.f; ar[bb] = 0.f; an[bb] = 0.f; }

    int buf = 0;
    for (int kt = 0; kt < 6; ++kt) {
      if (kt < 5) {
#pragma unroll
        for (int u = 0; u < 6; ++u) {
          int i = tid + SCAN_THREADS * u;
          if (i < 2048) {
            int bb = i >> 5, kq = i & 31;
            pf[u] = __ldcg((const float4*)(hsrc + bb * CC + (kt + 1) * 128 + kq * 4));
          }
        }
      }

      const int kof = kt * 128 + ks * 16;
      const int hof = ks * 16;
      const float* hbuf = h_s + buf * HSB;
#pragma unroll
      for (int q = 0; q < 4; ++q) {
        float4 wz = *(const float4*)(wzp + kof + q * 4);
        float4 wr = *(const float4*)(wrp + kof + q * 4);
        float4 wn = *(const float4*)(wnp + kof + q * 4);
#pragma unroll
        for (int bb = 0; bb < 8; ++bb) {
          float4 hv = *(const float4*)(hbuf + (bg + 8 * bb) * 132 + hof + q * 4);
          az[bb] = fmaf(hv.x, wz.x, fmaf(hv.y, wz.y,
                   fmaf(hv.z, wz.z, fmaf(hv.w, wz.w, az[bb]))));
          ar[bb] = fmaf(hv.x, wr.x, fmaf(hv.y, wr.y,
                   fmaf(hv.z, wr.z, fmaf(hv.w, wr.w, ar[bb]))));
          an[bb] = fmaf(hv.x, wn.x, fmaf(hv.y, wn.y,
                   fmaf(hv.z, wn.z, fmaf(hv.w, wn.w, an[bb]))));
        }
      }

      __syncthreads();
      if (kt < 5) {
#pragma unroll
        for (int u = 0; u < 6; ++u) {
          int i = tid + SCAN_THREADS * u;
          if (i < 2048) {
            int bb = i >> 5, kq = i & 31;
            *(float4*)(h_s + (buf ^ 1) * HSB + bb * 132 + kq * 4) = pf[u];
          }
        }
      }
      __syncthreads();
      buf ^= 1;
    }

#pragma unroll
    for (int bb = 0; bb < 8; ++bb) {
      const int b = bg + 8 * bb;
      p_s[((0 * 6 + j) * 64 + b) * 8 + ks] = az[bb];
      p_s[((1 * 6 + j) * 64 + b) * 8 + ks] = ar[bb];
      p_s[((2 * 6 + j) * 64 + b) * 8 + ks] = an[bb];
    }
    __syncthreads();

    float hz, hr, hn;
    {
      const float* pz = p_s + ((0 * 6 + je) * 64 + be) * 8;
      const float* pr = p_s + ((1 * 6 + je) * 64 + be) * 8;
      const float* pn = p_s + ((2 * 6 + je) * 64 + be) * 8;
      float4 a0 = *(const float4*)(pz), a1 = *(const float4*)(pz + 4);
      float4 b0 = *(const float4*)(pr), b1 = *(const float4*)(pr + 4);
      float4 d0 = *(const float4*)(pn), d1 = *(const float4*)(pn + 4);
      hz = (a0.x + a0.y + a0.z + a0.w) + (a1.x + a1.y + a1.z + a1.w);
      hr = (b0.x + b0.y + b0.z + b0.w) + (b1.x + b1.y + b1.z + b1.w);
      hn = (d0.x + d0.y + d0.z + d0.w) + (d1.x + d1.y + d1.z + d1.w);
    }

    float z  = 1.f / (1.f + expf(-(xz + hz + bz)));
    float rr = 1.f / (1.f + expf(-(xr + hr + br)));
    float nc = tanhf(xn + rr * (hn + bn));
    float hnew = (1.f - z) * nc + z * hold;

    __stcg(hdst + be * CC + ce, hnew);   // ordered before arrive by fence

    __threadfence();
    __syncthreads();
    if (tid == 0) atomicAdd(&g_bar, 1u);
    // (b) uncoalesced bookkeeping store overlaps the poll
    g_hs[(size_t)(s * BSZ + be) * CC + ce] = hnew;
    if (tid == 0) {
      const unsigned target = (unsigned)(s + 1) * gridDim.x;
      while (ldcg_u32(&g_bar) < target) { }   // (c) pure spin
    }
    __syncthreads();
  }
}

// ---------------------------------------------------------------------------
extern "C" void kernel_launch(void* const* d_in, const int* in_sizes, int n_in,
                              void* d_out, int out_size) {
  const float* x  = (const float*)d_in[0];
  const float* Wx = (const float*)d_in[1];
  const float* bx = (const float*)d_in[2];
  const float* Wh = (const float*)d_in[3];
  const float* bh = (const float*)d_in[4];
  const float* Wp = (const float*)d_in[5];
  float* out = (float*)d_out;

  void *p_xzrn = nullptr, *p_hs = nullptr;
  cudaGetSymbolAddress(&p_xzrn, g_xzrn);
  cudaGetSymbolAddress(&p_hs, g_hs);

  cudaFuncSetAttribute(scan_kernel,
                       cudaFuncAttributeMaxDynamicSharedMemorySize,
                       SCAN_SMEM_BYTES);

  // GEMM1: x_zrn[(n*64+b)][3C] = seq @ Wx^T + bx   (P=196, Q=64 remap)
  sgemm_kernel<<<dim3(C3 / 128, MROWS / 128), 256>>>(
      x, Wx, bx, (float*)p_xzrn, CC, C3, NSEQ, BSZ);

  // recurrence
  scan_kernel<<<SCAN_BLOCKS, SCAN_THREADS, SCAN_SMEM_BYTES>>>(Wh, bh);

  // GEMM3: out[b*196+n][C] = hs @ Wp^T              (P=64, Q=196 remap)
  sgemm_kernel<<<dim3(CC / 128, MROWS / 128), 256>>>(
      (const float*)p_hs, Wp, nullptr, out, CC, CC, BSZ, NSEQ);

  // reset scan state for the next replay
  reset_kernel<<<(BSZ * CC + 255) / 256, 256>>>();
}